// round 1
// baseline (speedup 1.0000x reference)
#include <cuda_runtime.h>
#include <cstddef>

// Bidirectional 2-layer LSTM, exploiting that the reference output only uses
// batch row 255 (outputs_btd[-1] indexes the batch axis). B collapses to 1.
//
// Pipeline (one CUDA graph, 3 kernel nodes):
//   phaseA: zx0[dir][s][1024] = x[255, t(s)] @ W{f,b}0[:128] + bias   (parallel)
//           + resets the inter-CTA counters (replay-safe)
//   phaseB: persistent 96-CTA kernel: 4 layer-direction recurrence engines
//           (fw-L0:16 CTAs, fw-L1:32, bw-L0:16, bw-L1:32), L1 pipelined one
//           step behind L0 via monotonic atomic counters through L2.
//   phaseC: logits[t] = [h1_fw[t], h1_bw[t]] @ Wd + bd                (parallel)

#define TT 512
#define HD 256
#define DD 128
#define BLAST 255

// ---------------- scratch (static device memory; no allocations) -----------
__device__ float g_zx0[2][TT][1024];   // layer0 x-part + bias, indexed by step s
__device__ float g_h0[2][TT][HD];      // layer0 outputs (by step s)
__device__ float g_h1[2][TT][HD];      // layer1 outputs (by step s)
__device__ unsigned g_cnt[2][2];       // [dir][layer] arrival counters

__device__ __forceinline__ float sigf(float x) { return 1.0f / (1.0f + expf(-x)); }

// ---------------- Phase A --------------------------------------------------
// grid 128 blocks x 256 threads: dir = bid>>6, 8 steps per block.
__global__ void phaseA(const float* __restrict__ x,
                       const float* __restrict__ Wf0, const float* __restrict__ bf0,
                       const float* __restrict__ Wb0, const float* __restrict__ bb0)
{
    if (blockIdx.x == 0 && threadIdx.x < 4)
        ((unsigned*)g_cnt)[threadIdx.x] = 0u;

    const int d     = blockIdx.x >> 6;      // 0 = fw, 1 = bw
    const int chunk = blockIdx.x & 63;      // 8 steps each
    const float* __restrict__ W    = d ? Wb0 : Wf0;
    const float* __restrict__ bias = d ? bb0 : bf0;

    __shared__ float xs[8][DD];
    const int tid = threadIdx.x;
    for (int i = tid; i < 8 * DD; i += 256) {
        int t8 = i >> 7, k = i & 127;
        int s = chunk * 8 + t8;
        int t = d ? (TT - 1 - s) : s;
        xs[t8][k] = x[(size_t)BLAST * TT * DD + (size_t)t * DD + k];
    }
    __syncthreads();

    for (int j = 0; j < 4; j++) {
        int col = tid + j * 256;
        float acc[8];
        float b = bias[col];
        #pragma unroll
        for (int t8 = 0; t8 < 8; t8++) acc[t8] = b;
        #pragma unroll 4
        for (int k = 0; k < DD; k++) {
            float w = W[k * 1024 + col];
            #pragma unroll
            for (int t8 = 0; t8 < 8; t8++) acc[t8] += xs[t8][k] * w;
        }
        #pragma unroll
        for (int t8 = 0; t8 < 8; t8++) g_zx0[d][chunk * 8 + t8][col] = acc[t8];
    }
}

// ---------------- Phase B: persistent recurrence engines --------------------
// 96 CTAs x 256 threads. Per dir: CTAs 0..15 = layer0, 16..47 = layer1.
__global__ void __launch_bounds__(256, 1) phaseB(
    const float* __restrict__ fw_state, const float* __restrict__ bw_state,
    const float* __restrict__ Wf0,
    const float* __restrict__ Wf1, const float* __restrict__ bf1,
    const float* __restrict__ Wb0,
    const float* __restrict__ Wb1, const float* __restrict__ bb1)
{
    const int bid = blockIdx.x;
    const int d   = bid / 48;
    const int r   = bid % 48;
    const int tid = threadIdx.x;
    const float* __restrict__ state = d ? bw_state : fw_state;

    if (r < 16) {
        // ================= layer-0 engine: 16 CTAs, 64 z-cols each =========
        const int c = r;                     // CTA index within engine
        const float* __restrict__ W = d ? Wb0 : Wf0;
        const int l = tid & 63;              // local z column (0..63)
        const int p = tid >> 6;              // k-partition (0..3), 64 K each
        const int q = l >> 4, j = l & 15;
        const int gcol = q * 256 + c * 16 + j;

        // recurrent weights (rows 128..383 of W0), resident in registers
        float w[64];
        #pragma unroll
        for (int i = 0; i < 64; i++)
            w[i] = W[(128 + p * 64 + i) * 1024 + gcol];

        __shared__ float hs[HD];
        __shared__ float red[256];
        __shared__ float zb[64];
        __shared__ float cs[16];

        hs[tid] = state[(size_t)BLAST * 1024 + 0 * 512 + 256 + tid];
        if (tid < 16) cs[tid] = state[(size_t)BLAST * 1024 + 0 * 512 + c * 16 + tid];
        __syncthreads();

        unsigned* cnt = &g_cnt[d][0];
        const int koff = p * 64;
        for (int s = 0; s < TT; s++) {
            float acc = 0.0f;
            #pragma unroll
            for (int i = 0; i < 64; i += 4) {
                float4 h4 = *(const float4*)&hs[koff + i];
                acc += w[i] * h4.x; acc += w[i + 1] * h4.y;
                acc += w[i + 2] * h4.z; acc += w[i + 3] * h4.w;
            }
            red[p * 64 + l] = acc;
            __syncthreads();
            if (tid < 64) {
                float z = red[tid] + red[64 + tid] + red[128 + tid] + red[192 + tid];
                zb[tid] = z + g_zx0[d][s][(tid >> 4) * 256 + c * 16 + (tid & 15)];
            }
            __syncthreads();
            if (tid < 16) {
                float zi = zb[tid], zj = zb[16 + tid], zf = zb[32 + tid], zo = zb[48 + tid];
                float cn = sigf(zf + 1.0f) * cs[tid] + sigf(zi) * tanhf(zj);
                float hn = sigf(zo) * tanhf(cn);
                cs[tid] = cn;
                __stcg(&g_h0[d][s][c * 16 + tid], hn);
            }
            __threadfence();
            __syncthreads();
            if (tid == 0) atomicAdd(cnt, 1u);
            if (s < TT - 1) {
                if (tid == 0) {
                    unsigned tgt = (unsigned)(16 * (s + 1));
                    while (atomicAdd(cnt, 0u) < tgt) __nanosleep(32);
                    __threadfence();
                }
                __syncthreads();
                hs[tid] = __ldcg(&g_h0[d][s][tid]);
                __syncthreads();
            }
        }
    } else {
        // ================= layer-1 engine: 32 CTAs, 32 z-cols each =========
        const int c1 = r - 16;
        const float* __restrict__ W    = d ? Wb1 : Wf1;
        const float* __restrict__ bias = d ? bb1 : bf1;
        const int l = tid & 31;              // local z column (0..31)
        const int p = tid >> 5;              // k-partition (0..7), 64 K each
        const int q = l >> 3, j = l & 7;
        const int gcol = q * 256 + c1 * 8 + j;

        // rows 0..255 = input (h0 from below), rows 256..511 = recurrent h1
        float w[64];
        #pragma unroll
        for (int i = 0; i < 64; i++)
            w[i] = W[(p * 64 + i) * 1024 + gcol];

        __shared__ float vs[512];            // [h0_t (0..255) ; h1_prev (256..511)]
        __shared__ float red[256];
        __shared__ float zb[32];
        __shared__ float cs[8];

        vs[256 + tid] = state[(size_t)BLAST * 1024 + 1 * 512 + 256 + tid];
        if (tid < 8) cs[tid] = state[(size_t)BLAST * 1024 + 1 * 512 + c1 * 8 + tid];
        __syncthreads();

        unsigned* cnt0 = &g_cnt[d][0];
        unsigned* cnt1 = &g_cnt[d][1];
        const int koff = p * 64;
        for (int s = 0; s < TT; s++) {
            // wait for layer0 output at step s
            if (tid == 0) {
                unsigned tgt = (unsigned)(16 * (s + 1));
                while (atomicAdd(cnt0, 0u) < tgt) __nanosleep(32);
                __threadfence();
            }
            __syncthreads();
            vs[tid] = __ldcg(&g_h0[d][s][tid]);
            __syncthreads();

            float acc = 0.0f;
            #pragma unroll
            for (int i = 0; i < 64; i += 4) {
                float4 h4 = *(const float4*)&vs[koff + i];
                acc += w[i] * h4.x; acc += w[i + 1] * h4.y;
                acc += w[i + 2] * h4.z; acc += w[i + 3] * h4.w;
            }
            red[p * 32 + l] = acc;
            __syncthreads();
            if (tid < 32) {
                float z = 0.0f;
                #pragma unroll
                for (int pp = 0; pp < 8; pp++) z += red[pp * 32 + tid];
                zb[tid] = z + bias[(tid >> 3) * 256 + c1 * 8 + (tid & 7)];
            }
            __syncthreads();
            if (tid < 8) {
                float zi = zb[tid], zj = zb[8 + tid], zf = zb[16 + tid], zo = zb[24 + tid];
                float cn = sigf(zf + 1.0f) * cs[tid] + sigf(zi) * tanhf(zj);
                float hn = sigf(zo) * tanhf(cn);
                cs[tid] = cn;
                __stcg(&g_h1[d][s][c1 * 8 + tid], hn);
            }
            __threadfence();
            __syncthreads();
            if (tid == 0) atomicAdd(cnt1, 1u);
            if (s < TT - 1) {
                if (tid == 0) {
                    unsigned tgt = (unsigned)(32 * (s + 1));
                    while (atomicAdd(cnt1, 0u) < tgt) __nanosleep(32);
                    __threadfence();
                }
                __syncthreads();
                vs[256 + tid] = __ldcg(&g_h1[d][s][tid]);
                __syncthreads();
            }
        }
    }
}

// ---------------- Phase C: final dense -------------------------------------
// grid 64 blocks x 128 threads, 8 timesteps per block.
__global__ void phaseC(const float* __restrict__ Wd, const float* __restrict__ bd,
                       float* __restrict__ out)
{
    const int chunk = blockIdx.x;
    const int o = threadIdx.x;
    __shared__ float hsm[8][512];
    for (int i = threadIdx.x; i < 8 * 512; i += 128) {
        int t8 = i >> 9, k = i & 511;
        int t = chunk * 8 + t8;
        hsm[t8][k] = (k < 256) ? g_h1[0][t][k] : g_h1[1][TT - 1 - t][k - 256];
    }
    __syncthreads();
    float b = bd[o];
    float acc[8];
    #pragma unroll
    for (int t8 = 0; t8 < 8; t8++) acc[t8] = b;
    #pragma unroll 4
    for (int k = 0; k < 512; k++) {
        float w = Wd[k * 128 + o];
        #pragma unroll
        for (int t8 = 0; t8 < 8; t8++) acc[t8] += hsm[t8][k] * w;
    }
    #pragma unroll
    for (int t8 = 0; t8 < 8; t8++) out[(chunk * 8 + t8) * 128 + o] = acc[t8];
}

// ---------------- launch ----------------------------------------------------
extern "C" void kernel_launch(void* const* d_in, const int* in_sizes, int n_in,
                              void* d_out, int out_size)
{
    (void)in_sizes; (void)n_in; (void)out_size;
    const float* x        = (const float*)d_in[0];
    const float* fw_state = (const float*)d_in[1];
    const float* bw_state = (const float*)d_in[2];
    const float* Wf0 = (const float*)d_in[3];
    const float* bf0 = (const float*)d_in[4];
    const float* Wf1 = (const float*)d_in[5];
    const float* bf1 = (const float*)d_in[6];
    const float* Wb0 = (const float*)d_in[7];
    const float* bb0 = (const float*)d_in[8];
    const float* Wb1 = (const float*)d_in[9];
    const float* bb1 = (const float*)d_in[10];
    const float* Wd  = (const float*)d_in[11];
    const float* bd  = (const float*)d_in[12];

    phaseA<<<128, 256>>>(x, Wf0, bf0, Wb0, bb0);
    phaseB<<<96, 256>>>(fw_state, bw_state, Wf0, Wf1, bf1, Wb0, Wb1, bb1);
    phaseC<<<64, 128>>>(Wd, bd, (float*)d_out);
}

// round 2
// speedup vs baseline: 1.4012x; 1.4012x over previous
#include <cuda_runtime.h>
#include <cstddef>

// Bidirectional 2-layer LSTM; only batch row 255 feeds the output, so B
// collapses to 1 and the whole network is 4 pipelined GEMV recurrence chains.
//
//   phaseA: zx0[dir][s][1024] = x[255, t(s)] @ W{f,b}0[:128] + bias  (+ counter reset)
//   phaseB: persistent 96-CTA kernel: fw-L0:16, fw-L1:32, bw-L0:16, bw-L1:32
//           sync via monotonic counters: red.release.gpu.add (producer) and
//           ld.acquire.gpu polling (consumer) — NO atomic polls (they serialize
//           in the LTS atomic ALU and were the round-1 bottleneck).
//   phaseC: logits[t] = [h1_fw[t], h1_bw[t]] @ Wd + bd

#define TT 512
#define HD 256
#define DD 128
#define BLAST 255

// ---------------- scratch (static device memory; no allocations) -----------
__device__ float g_zx0[2][TT][1024];   // layer0 x-part + bias, by step s
__device__ float g_h0[2][TT][HD];      // layer0 outputs (by step s)
__device__ float g_h1[2][TT][HD];      // layer1 outputs (by step s)
__device__ unsigned g_cnt[2][2];       // [dir][layer] arrival counters

__device__ __forceinline__ float sigf(float x) { return 1.0f / (1.0f + expf(-x)); }

__device__ __forceinline__ void rel_add(unsigned* p) {
    asm volatile("red.release.gpu.global.add.u32 [%0], 1;" :: "l"(p) : "memory");
}
__device__ __forceinline__ unsigned acq_ld(const unsigned* p) {
    unsigned v;
    asm volatile("ld.acquire.gpu.global.u32 %0, [%1];" : "=r"(v) : "l"(p) : "memory");
    return v;
}

// ---------------- Phase A --------------------------------------------------
// 128 blocks x 256 threads: dir = bid>>6, 8 steps per block.
// Merged column loop: 32 accumulators, k-unroll 4 -> 16 outstanding W loads.
__global__ void phaseA(const float* __restrict__ x,
                       const float* __restrict__ Wf0, const float* __restrict__ bf0,
                       const float* __restrict__ Wb0, const float* __restrict__ bb0)
{
    if (blockIdx.x == 0 && threadIdx.x < 4)
        ((unsigned*)g_cnt)[threadIdx.x] = 0u;

    const int d     = blockIdx.x >> 6;      // 0 = fw, 1 = bw
    const int chunk = blockIdx.x & 63;      // 8 steps each
    const float* __restrict__ W    = d ? Wb0 : Wf0;
    const float* __restrict__ bias = d ? bb0 : bf0;

    __shared__ float xs[8][DD];
    const int tid = threadIdx.x;
    for (int i = tid; i < 8 * DD; i += 256) {
        int t8 = i >> 7, k = i & 127;
        int s = chunk * 8 + t8;
        int t = d ? (TT - 1 - s) : s;
        xs[t8][k] = x[(size_t)BLAST * TT * DD + (size_t)t * DD + k];
    }
    __syncthreads();

    float acc[4][8];
    #pragma unroll
    for (int j = 0; j < 4; j++) {
        float b = bias[tid + j * 256];
        #pragma unroll
        for (int t8 = 0; t8 < 8; t8++) acc[j][t8] = b;
    }
    #pragma unroll 4
    for (int k = 0; k < DD; k++) {
        float xv[8];
        #pragma unroll
        for (int t8 = 0; t8 < 8; t8++) xv[t8] = xs[t8][k];
        #pragma unroll
        for (int j = 0; j < 4; j++) {
            float w = W[k * 1024 + tid + j * 256];
            #pragma unroll
            for (int t8 = 0; t8 < 8; t8++) acc[j][t8] += xv[t8] * w;
        }
    }
    #pragma unroll
    for (int j = 0; j < 4; j++)
        #pragma unroll
        for (int t8 = 0; t8 < 8; t8++)
            g_zx0[d][chunk * 8 + t8][tid + j * 256] = acc[j][t8];
}

// ---------------- Phase B: persistent recurrence engines --------------------
// 96 CTAs x 256 threads. Per dir: CTAs 0..15 = layer0, 16..47 = layer1.
__global__ void __launch_bounds__(256, 1) phaseB(
    const float* __restrict__ fw_state, const float* __restrict__ bw_state,
    const float* __restrict__ Wf0,
    const float* __restrict__ Wf1, const float* __restrict__ bf1,
    const float* __restrict__ Wb0,
    const float* __restrict__ Wb1, const float* __restrict__ bb1)
{
    const int bid = blockIdx.x;
    const int d   = bid / 48;
    const int r   = bid % 48;
    const int tid = threadIdx.x;
    const float* __restrict__ state = d ? bw_state : fw_state;

    if (r < 16) {
        // ================= layer-0 engine: 16 CTAs, 64 z-cols each =========
        const int c = r;
        const float* __restrict__ W = d ? Wb0 : Wf0;
        const int l = tid & 63;              // local z column (0..63)
        const int p = tid >> 6;              // k-partition (0..3), 64 K each
        const int q = l >> 4, j = l & 15;
        const int gcol = q * 256 + c * 16 + j;

        // recurrent weights (rows 128..383 of W0), resident in registers
        float w[64];
        #pragma unroll
        for (int i = 0; i < 64; i++)
            w[i] = W[(128 + p * 64 + i) * 1024 + gcol];

        __shared__ float hs[HD];
        __shared__ float red[256];
        __shared__ float cs[16];

        hs[tid] = state[(size_t)BLAST * 1024 + 256 + tid];
        if (tid < 16) cs[tid] = state[(size_t)BLAST * 1024 + c * 16 + tid];
        __syncthreads();

        unsigned* cnt = &g_cnt[d][0];
        const int koff = p * 64;
        for (int s = 0; s < TT; s++) {
            float acc = 0.0f;
            #pragma unroll
            for (int i = 0; i < 64; i += 4) {
                float4 h4 = *(const float4*)&hs[koff + i];
                acc += w[i] * h4.x; acc += w[i + 1] * h4.y;
                acc += w[i + 2] * h4.z; acc += w[i + 3] * h4.w;
            }
            red[p * 64 + l] = acc;
            __syncthreads();
            if (tid < 16) {
                float z[4];
                #pragma unroll
                for (int g = 0; g < 4; g++) {
                    int li = g * 16 + tid;
                    z[g] = red[li] + red[64 + li] + red[128 + li] + red[192 + li]
                         + g_zx0[d][s][g * 256 + c * 16 + tid];
                }
                float cn = sigf(z[2] + 1.0f) * cs[tid] + sigf(z[0]) * tanhf(z[1]);
                float hn = sigf(z[3]) * tanhf(cn);
                cs[tid] = cn;
                __stcg(&g_h0[d][s][c * 16 + tid], hn);
                __syncwarp(0x0000ffffu);
                if (tid == 0) rel_add(cnt);
            }
            if (s < TT - 1) {
                if (tid == 0) {
                    unsigned tgt = 16u * (unsigned)(s + 1);
                    while (acq_ld(cnt) < tgt) { }
                }
                __syncthreads();
                hs[tid] = __ldcg(&g_h0[d][s][tid]);
                __syncthreads();
            }
        }
    } else {
        // ================= layer-1 engine: 32 CTAs, 32 z-cols each =========
        const int c1 = r - 16;
        const float* __restrict__ W    = d ? Wb1 : Wf1;
        const float* __restrict__ bias = d ? bb1 : bf1;
        const int l = tid & 31;              // local z column (0..31)
        const int p = tid >> 5;              // k-partition (0..7), 64 K each
        const int q = l >> 3, j = l & 7;
        const int gcol = q * 256 + c1 * 8 + j;

        // rows 0..255 = input (h0 from below), rows 256..511 = recurrent h1
        float w[64];
        #pragma unroll
        for (int i = 0; i < 64; i++)
            w[i] = W[(p * 64 + i) * 1024 + gcol];

        __shared__ float vs[512];            // [h0_t (0..255) ; h1_prev (256..511)]
        __shared__ float red[256];
        __shared__ float cs[8];

        float bz[4];
        if (tid < 8) {
            #pragma unroll
            for (int g = 0; g < 4; g++) bz[g] = bias[g * 256 + c1 * 8 + tid];
            cs[tid] = state[(size_t)BLAST * 1024 + 512 + c1 * 8 + tid];
        }
        vs[256 + tid] = state[(size_t)BLAST * 1024 + 512 + 256 + tid];
        __syncthreads();

        unsigned* cnt0 = &g_cnt[d][0];
        unsigned* cnt1 = &g_cnt[d][1];
        const int koff = p * 64;
        for (int s = 0; s < TT; s++) {
            // wait for layer0 output at step s
            if (tid == 0) {
                unsigned tgt = 16u * (unsigned)(s + 1);
                while (acq_ld(cnt0) < tgt) { }
            }
            __syncthreads();
            vs[tid] = __ldcg(&g_h0[d][s][tid]);
            __syncthreads();

            float acc = 0.0f;
            #pragma unroll
            for (int i = 0; i < 64; i += 4) {
                float4 h4 = *(const float4*)&vs[koff + i];
                acc += w[i] * h4.x; acc += w[i + 1] * h4.y;
                acc += w[i + 2] * h4.z; acc += w[i + 3] * h4.w;
            }
            red[p * 32 + l] = acc;
            __syncthreads();
            if (tid < 8) {
                float z[4];
                #pragma unroll
                for (int g = 0; g < 4; g++) {
                    float zz = bz[g];
                    #pragma unroll
                    for (int pp = 0; pp < 8; pp++) zz += red[pp * 32 + g * 8 + tid];
                    z[g] = zz;
                }
                float cn = sigf(z[2] + 1.0f) * cs[tid] + sigf(z[0]) * tanhf(z[1]);
                float hn = sigf(z[3]) * tanhf(cn);
                cs[tid] = cn;
                __stcg(&g_h1[d][s][c1 * 8 + tid], hn);
                __syncwarp(0x000000ffu);
                if (tid == 0) rel_add(cnt1);
            }
            if (s < TT - 1) {
                if (tid == 0) {
                    unsigned tgt = 32u * (unsigned)(s + 1);
                    while (acq_ld(cnt1) < tgt) { }
                }
                __syncthreads();
                vs[256 + tid] = __ldcg(&g_h1[d][s][tid]);
                __syncthreads();
            }
        }
    }
}

// ---------------- Phase C: final dense -------------------------------------
// 64 blocks x 128 threads, 8 timesteps per block.
__global__ void phaseC(const float* __restrict__ Wd, const float* __restrict__ bd,
                       float* __restrict__ out)
{
    const int chunk = blockIdx.x;
    const int o = threadIdx.x;
    __shared__ float hsm[8][512];
    for (int i = threadIdx.x; i < 8 * 512; i += 128) {
        int t8 = i >> 9, k = i & 511;
        int t = chunk * 8 + t8;
        hsm[t8][k] = (k < 256) ? g_h1[0][t][k] : g_h1[1][TT - 1 - t][k - 256];
    }
    __syncthreads();
    float b = bd[o];
    float acc[8];
    #pragma unroll
    for (int t8 = 0; t8 < 8; t8++) acc[t8] = b;
    #pragma unroll 8
    for (int k = 0; k < 512; k++) {
        float w = Wd[k * 128 + o];
        #pragma unroll
        for (int t8 = 0; t8 < 8; t8++) acc[t8] += hsm[t8][k] * w;
    }
    #pragma unroll
    for (int t8 = 0; t8 < 8; t8++) out[(chunk * 8 + t8) * 128 + o] = acc[t8];
}

// ---------------- launch ----------------------------------------------------
extern "C" void kernel_launch(void* const* d_in, const int* in_sizes, int n_in,
                              void* d_out, int out_size)
{
    (void)in_sizes; (void)n_in; (void)out_size;
    const float* x        = (const float*)d_in[0];
    const float* fw_state = (const float*)d_in[1];
    const float* bw_state = (const float*)d_in[2];
    const float* Wf0 = (const float*)d_in[3];
    const float* bf0 = (const float*)d_in[4];
    const float* Wf1 = (const float*)d_in[5];
    const float* bf1 = (const float*)d_in[6];
    const float* Wb0 = (const float*)d_in[7];
    const float* bb0 = (const float*)d_in[8];
    const float* Wb1 = (const float*)d_in[9];
    const float* bb1 = (const float*)d_in[10];
    const float* Wd  = (const float*)d_in[11];
    const float* bd  = (const float*)d_in[12];

    phaseA<<<128, 256>>>(x, Wf0, bf0, Wb0, bb0);
    phaseB<<<96, 256>>>(fw_state, bw_state, Wf0, Wf1, bf1, Wb0, Wb1, bb1);
    phaseC<<<64, 128>>>(Wd, bd, (float*)d_out);
}

// round 5
// speedup vs baseline: 1.4941x; 1.0663x over previous
#include <cuda_runtime.h>
#include <cstddef>

// Bidirectional 2-layer LSTM; only batch row 255 feeds the output (B -> 1).
// Round 5: exact Round-2 structure (proven: counters + release-red/acquire-ld)
// with three safe deltas: fast MUFU gate math, zx0 prefetch, wider phaseA.

#define TT 512
#define HD 256
#define DD 128
#define BLAST 255

// ---------------- scratch (static device memory; no allocations) -----------
__device__ float g_zx0[2][TT][1024];   // layer0 x-part + bias, by step s
__device__ float g_h0[2][TT][HD];      // layer0 outputs (by step s)
__device__ float g_h1[2][TT][HD];      // layer1 outputs (by step s)
__device__ unsigned g_cnt[2][2];       // [dir][layer] arrival counters

// fast saturating gate math (MUFU EX2/RCP based; no NaN paths):
//  sig(x)  = 1/(1+e^-x):  e^inf=inf -> 1/inf=0 ; e^-inf=0 -> 1
//  tanh(x) = 1 - 2/(e^2x+1): saturates to +-1
__device__ __forceinline__ float fsig(float x) {
    return __fdividef(1.0f, 1.0f + __expf(-x));
}
__device__ __forceinline__ float ftanh(float x) {
    return 1.0f - __fdividef(2.0f, __expf(2.0f * x) + 1.0f);
}

__device__ __forceinline__ void rel_add(unsigned* p) {
    asm volatile("red.release.gpu.global.add.u32 [%0], 1;" :: "l"(p) : "memory");
}
__device__ __forceinline__ unsigned acq_ld(const unsigned* p) {
    unsigned v;
    asm volatile("ld.acquire.gpu.global.u32 %0, [%1];" : "=r"(v) : "l"(p) : "memory");
    return v;
}

// ---------------- Phase A --------------------------------------------------
// 256 blocks x 256 threads: dir = bid>>7, 4 steps per block.
__global__ void phaseA(const float* __restrict__ x,
                       const float* __restrict__ Wf0, const float* __restrict__ bf0,
                       const float* __restrict__ Wb0, const float* __restrict__ bb0)
{
    if (blockIdx.x == 0 && threadIdx.x < 4)
        ((unsigned*)g_cnt)[threadIdx.x] = 0u;

    const int d     = blockIdx.x >> 7;      // 0 = fw, 1 = bw
    const int chunk = blockIdx.x & 127;     // 4 steps each
    const float* __restrict__ W    = d ? Wb0 : Wf0;
    const float* __restrict__ bias = d ? bb0 : bf0;

    __shared__ float xs[4][DD];
    const int tid = threadIdx.x;
    for (int i = tid; i < 4 * DD; i += 256) {
        int t4 = i >> 7, k = i & 127;
        int s = chunk * 4 + t4;
        int t = d ? (TT - 1 - s) : s;
        xs[t4][k] = x[(size_t)BLAST * TT * DD + (size_t)t * DD + k];
    }
    __syncthreads();

    float acc[4][4];
    #pragma unroll
    for (int j = 0; j < 4; j++) {
        float b = bias[tid + j * 256];
        #pragma unroll
        for (int t4 = 0; t4 < 4; t4++) acc[j][t4] = b;
    }
    #pragma unroll 4
    for (int k = 0; k < DD; k++) {
        float xv[4];
        #pragma unroll
        for (int t4 = 0; t4 < 4; t4++) xv[t4] = xs[t4][k];
        #pragma unroll
        for (int j = 0; j < 4; j++) {
            float w = W[k * 1024 + tid + j * 256];
            #pragma unroll
            for (int t4 = 0; t4 < 4; t4++) acc[j][t4] += xv[t4] * w;
        }
    }
    #pragma unroll
    for (int j = 0; j < 4; j++)
        #pragma unroll
        for (int t4 = 0; t4 < 4; t4++)
            g_zx0[d][chunk * 4 + t4][tid + j * 256] = acc[j][t4];
}

// ---------------- Phase B: persistent recurrence engines --------------------
// 96 CTAs x 256 threads. Per dir: CTAs 0..15 = layer0, 16..47 = layer1.
__global__ void __launch_bounds__(256, 1) phaseB(
    const float* __restrict__ fw_state, const float* __restrict__ bw_state,
    const float* __restrict__ Wf0,
    const float* __restrict__ Wf1, const float* __restrict__ bf1,
    const float* __restrict__ Wb0,
    const float* __restrict__ Wb1, const float* __restrict__ bb1)
{
    const int bid = blockIdx.x;
    const int d   = bid / 48;
    const int r   = bid % 48;
    const int tid = threadIdx.x;
    const float* __restrict__ state = d ? bw_state : fw_state;

    if (r < 16) {
        // ================= layer-0 engine: 16 CTAs, 64 z-cols each =========
        const int c = r;
        const float* __restrict__ W = d ? Wb0 : Wf0;
        const int l = tid & 63;              // local z column (0..63)
        const int p = tid >> 6;              // k-partition (0..3), 64 K each
        const int q = l >> 4, j = l & 15;
        const int gcol = q * 256 + c * 16 + j;

        // recurrent weights (rows 128..383 of W0), resident in registers
        float w[64];
        #pragma unroll
        for (int i = 0; i < 64; i++)
            w[i] = W[(128 + p * 64 + i) * 1024 + gcol];

        __shared__ float hs[HD];
        __shared__ float red[256];
        __shared__ float cs[16];

        hs[tid] = state[(size_t)BLAST * 1024 + 256 + tid];
        if (tid < 16) cs[tid] = state[(size_t)BLAST * 1024 + c * 16 + tid];
        __syncthreads();

        unsigned* cnt = &g_cnt[d][0];
        const int koff = p * 64;
        for (int s = 0; s < TT; s++) {
            // prefetch zx0[s] into registers (ready since phaseA; hides L2)
            float zx[4];
            if (tid < 16) {
                #pragma unroll
                for (int g = 0; g < 4; g++)
                    zx[g] = __ldcg(&g_zx0[d][s][g * 256 + c * 16 + tid]);
            }

            float acc = 0.0f;
            #pragma unroll
            for (int i = 0; i < 64; i += 4) {
                float4 h4 = *(const float4*)&hs[koff + i];
                acc += w[i] * h4.x; acc += w[i + 1] * h4.y;
                acc += w[i + 2] * h4.z; acc += w[i + 3] * h4.w;
            }
            red[p * 64 + l] = acc;
            __syncthreads();
            if (tid < 16) {
                float z[4];
                #pragma unroll
                for (int g = 0; g < 4; g++) {
                    int li = g * 16 + tid;
                    z[g] = red[li] + red[64 + li] + red[128 + li] + red[192 + li]
                         + zx[g];
                }
                float cn = fsig(z[2] + 1.0f) * cs[tid] + fsig(z[0]) * ftanh(z[1]);
                float hn = fsig(z[3]) * ftanh(cn);
                cs[tid] = cn;
                __stcg(&g_h0[d][s][c * 16 + tid], hn);
                __syncwarp(0x0000ffffu);
                if (tid == 0) rel_add(cnt);
            }
            if (s < TT - 1) {
                if (tid == 0) {
                    unsigned tgt = 16u * (unsigned)(s + 1);
                    while (acq_ld(cnt) < tgt) { }
                }
                __syncthreads();
                hs[tid] = __ldcg(&g_h0[d][s][tid]);
                __syncthreads();
            }
        }
    } else {
        // ================= layer-1 engine: 32 CTAs, 32 z-cols each =========
        const int c1 = r - 16;
        const float* __restrict__ W    = d ? Wb1 : Wf1;
        const float* __restrict__ bias = d ? bb1 : bf1;
        const int l = tid & 31;              // local z column (0..31)
        const int p = tid >> 5;              // k-partition (0..7), 64 K each
        const int q = l >> 3, j = l & 7;
        const int gcol = q * 256 + c1 * 8 + j;

        // rows 0..255 = input (h0 from below), rows 256..511 = recurrent h1
        float w[64];
        #pragma unroll
        for (int i = 0; i < 64; i++)
            w[i] = W[(p * 64 + i) * 1024 + gcol];

        __shared__ float vs[512];            // [h0_t (0..255) ; h1_prev (256..511)]
        __shared__ float red[256];
        __shared__ float cs[8];

        float bz[4];
        if (tid < 8) {
            #pragma unroll
            for (int g = 0; g < 4; g++) bz[g] = bias[g * 256 + c1 * 8 + tid];
            cs[tid] = state[(size_t)BLAST * 1024 + 512 + c1 * 8 + tid];
        }
        vs[256 + tid] = state[(size_t)BLAST * 1024 + 512 + 256 + tid];
        __syncthreads();

        unsigned* cnt0 = &g_cnt[d][0];
        unsigned* cnt1 = &g_cnt[d][1];
        const int koff = p * 64;
        for (int s = 0; s < TT; s++) {
            // wait for layer0 output at step s
            if (tid == 0) {
                unsigned tgt = 16u * (unsigned)(s + 1);
                while (acq_ld(cnt0) < tgt) { }
            }
            __syncthreads();
            vs[tid] = __ldcg(&g_h0[d][s][tid]);
            __syncthreads();

            float acc = 0.0f;
            #pragma unroll
            for (int i = 0; i < 64; i += 4) {
                float4 h4 = *(const float4*)&vs[koff + i];
                acc += w[i] * h4.x; acc += w[i + 1] * h4.y;
                acc += w[i + 2] * h4.z; acc += w[i + 3] * h4.w;
            }
            red[p * 32 + l] = acc;
            __syncthreads();
            if (tid < 8) {
                float z[4];
                #pragma unroll
                for (int g = 0; g < 4; g++) {
                    float zz = bz[g];
                    #pragma unroll
                    for (int pp = 0; pp < 8; pp++) zz += red[pp * 32 + g * 8 + tid];
                    z[g] = zz;
                }
                float cn = fsig(z[2] + 1.0f) * cs[tid] + fsig(z[0]) * ftanh(z[1]);
                float hn = fsig(z[3]) * ftanh(cn);
                cs[tid] = cn;
                __stcg(&g_h1[d][s][c1 * 8 + tid], hn);
                __syncwarp(0x000000ffu);
                if (tid == 0) rel_add(cnt1);
            }
            if (s < TT - 1) {
                if (tid == 0) {
                    unsigned tgt = 32u * (unsigned)(s + 1);
                    while (acq_ld(cnt1) < tgt) { }
                }
                __syncthreads();
                vs[256 + tid] = __ldcg(&g_h1[d][s][tid]);
                __syncthreads();
            }
        }
    }
}

// ---------------- Phase C: final dense -------------------------------------
// 64 blocks x 128 threads, 8 timesteps per block.
__global__ void phaseC(const float* __restrict__ Wd, const float* __restrict__ bd,
                       float* __restrict__ out)
{
    const int chunk = blockIdx.x;
    const int o = threadIdx.x;
    __shared__ float hsm[8][512];
    for (int i = threadIdx.x; i < 8 * 512; i += 128) {
        int t8 = i >> 9, k = i & 511;
        int t = chunk * 8 + t8;
        hsm[t8][k] = (k < 256) ? g_h1[0][t][k] : g_h1[1][TT - 1 - t][k - 256];
    }
    __syncthreads();
    float b = bd[o];
    float acc[8];
    #pragma unroll
    for (int t8 = 0; t8 < 8; t8++) acc[t8] = b;
    #pragma unroll 8
    for (int k = 0; k < 512; k++) {
        float w = Wd[k * 128 + o];
        #pragma unroll
        for (int t8 = 0; t8 < 8; t8++) acc[t8] += hsm[t8][k] * w;
    }
    #pragma unroll
    for (int t8 = 0; t8 < 8; t8++) out[(chunk * 8 + t8) * 128 + o] = acc[t8];
}

// ---------------- launch ----------------------------------------------------
extern "C" void kernel_launch(void* const* d_in, const int* in_sizes, int n_in,
                              void* d_out, int out_size)
{
    (void)in_sizes; (void)n_in; (void)out_size;
    const float* x        = (const float*)d_in[0];
    const float* fw_state = (const float*)d_in[1];
    const float* bw_state = (const float*)d_in[2];
    const float* Wf0 = (const float*)d_in[3];
    const float* bf0 = (const float*)d_in[4];
    const float* Wf1 = (const float*)d_in[5];
    const float* bf1 = (const float*)d_in[6];
    const float* Wb0 = (const float*)d_in[7];
    const float* bb0 = (const float*)d_in[8];
    const float* Wb1 = (const float*)d_in[9];
    const float* bb1 = (const float*)d_in[10];
    const float* Wd  = (const float*)d_in[11];
    const float* bd  = (const float*)d_in[12];

    phaseA<<<256, 256>>>(x, Wf0, bf0, Wb0, bb0);
    phaseB<<<96, 256>>>(fw_state, bw_state, Wf0, Wf1, bf1, Wb0, Wb1, bb1);
    phaseC<<<64, 128>>>(Wd, bd, (float*)d_out);
}